// round 7
// baseline (speedup 1.0000x reference)
#include <cuda_runtime.h>
#include <math.h>

#define BATCH 4
#define SEQ   2048
#define DIM   1024

// ---- static device scratch (no allocations allowed) ----
__device__ float g_Q[BATCH * SEQ * DIM];
__device__ float g_K[BATCH * SEQ * DIM];
__device__ float g_V[BATCH * SEQ * DIM];
__device__ float g_mags[BATCH * SEQ];
__device__ float g_mean;
__device__ float g_Wscratch[BATCH * SEQ * SEQ];  // fallback if weights not in d_out

// ============================================================
// per-token L2 norms (float4 loads + warp-shuffle reduction)
// ============================================================
__global__ __launch_bounds__(256) void mags_kernel(const float* __restrict__ E) {
    const int token = blockIdx.x;                  // 0 .. B*S-1
    const float* x = E + (size_t)token * DIM;
    const int tid = threadIdx.x;
    // DIM/4 = 256 float4 per row, one per thread
    float4 v = *(const float4*)(x + tid * 4);
    float s = v.x * v.x + v.y * v.y + v.z * v.z + v.w * v.w;
#pragma unroll
    for (int off = 16; off > 0; off >>= 1)
        s += __shfl_xor_sync(0xFFFFFFFFu, s, off);
    __shared__ float red[8];
    if ((tid & 31) == 0) red[tid >> 5] = s;
    __syncthreads();
    if (tid < 8) {
        float t = red[tid];
#pragma unroll
        for (int off = 4; off > 0; off >>= 1)
            t += __shfl_xor_sync(0xFFu, t, off);
        if (tid == 0) g_mags[token] = sqrtf(t);
    }
}

// ============================================================
// global mean of outer product:  mean = (1/(B*S*S)) * sum_b (sum_s mags)^2
// fp64 accumulation to minimize threshold flips vs fp32 reference
// ============================================================
__global__ __launch_bounds__(256) void mean_kernel() {
    __shared__ double red[256];
    const int tid = threadIdx.x;
    double total = 0.0;
    for (int b = 0; b < BATCH; ++b) {
        double s = 0.0;
        for (int i = tid; i < SEQ; i += 256) s += (double)g_mags[b * SEQ + i];
        red[tid] = s;
        __syncthreads();
        for (int off = 128; off > 0; off >>= 1) {
            if (tid < off) red[tid] += red[tid + off];
            __syncthreads();
        }
        if (tid == 0) total += red[0] * red[0];
        __syncthreads();
    }
    if (tid == 0)
        g_mean = (float)(total / ((double)BATCH * (double)SEQ * (double)SEQ));
}

// ============================================================
// Double-buffered SGEMM mainloops:
// 128x128 tile, BK=16, 256 threads, 8x8 per thread.
// ============================================================

// NT: C[m,n] = sum_k A[m,k]*B[n,k]; both row-major, K contiguous.
__device__ __forceinline__ void mm_nt(const float* __restrict__ A, int lda,
                                      const float* __restrict__ B, int ldb,
                                      int K, float (&acc)[8][8],
                                      float (*As)[16][128], float (*Bs)[16][128]) {
    const int tid = threadIdx.x;
    const int lr = tid >> 2;              // 0..63
    const int lc = (tid & 3) << 2;        // 0,4,8,12
    const int ty = tid >> 4, tx = tid & 15;

    float4 pa[2], pb[2];
#pragma unroll
    for (int r = 0; r < 2; ++r) {
        const int row = lr + 64 * r;
        pa[r] = *(const float4*)(A + (size_t)row * lda + lc);
        pb[r] = *(const float4*)(B + (size_t)row * ldb + lc);
    }
    int buf = 0;
#pragma unroll
    for (int r = 0; r < 2; ++r) {
        const int row = lr + 64 * r;
        As[buf][lc + 0][row] = pa[r].x; As[buf][lc + 1][row] = pa[r].y;
        As[buf][lc + 2][row] = pa[r].z; As[buf][lc + 3][row] = pa[r].w;
        Bs[buf][lc + 0][row] = pb[r].x; Bs[buf][lc + 1][row] = pb[r].y;
        Bs[buf][lc + 2][row] = pb[r].z; Bs[buf][lc + 3][row] = pb[r].w;
    }
    __syncthreads();

    for (int k0 = 16; k0 <= K; k0 += 16) {
        const bool more = (k0 < K);
        if (more) {
#pragma unroll
            for (int r = 0; r < 2; ++r) {
                const int row = lr + 64 * r;
                pa[r] = *(const float4*)(A + (size_t)row * lda + k0 + lc);
                pb[r] = *(const float4*)(B + (size_t)row * ldb + k0 + lc);
            }
        }
#pragma unroll
        for (int kk = 0; kk < 16; ++kk) {
            float ar[8], br[8];
            *(float4*)&ar[0] = *(const float4*)&As[buf][kk][ty * 8];
            *(float4*)&ar[4] = *(const float4*)&As[buf][kk][ty * 8 + 4];
            *(float4*)&br[0] = *(const float4*)&Bs[buf][kk][tx * 8];
            *(float4*)&br[4] = *(const float4*)&Bs[buf][kk][tx * 8 + 4];
#pragma unroll
            for (int i = 0; i < 8; ++i)
#pragma unroll
                for (int j = 0; j < 8; ++j)
                    acc[i][j] = fmaf(ar[i], br[j], acc[i][j]);
        }
        if (more) {
            buf ^= 1;
#pragma unroll
            for (int r = 0; r < 2; ++r) {
                const int row = lr + 64 * r;
                As[buf][lc + 0][row] = pa[r].x; As[buf][lc + 1][row] = pa[r].y;
                As[buf][lc + 2][row] = pa[r].z; As[buf][lc + 3][row] = pa[r].w;
                Bs[buf][lc + 0][row] = pb[r].x; Bs[buf][lc + 1][row] = pb[r].y;
                Bs[buf][lc + 2][row] = pb[r].z; Bs[buf][lc + 3][row] = pb[r].w;
            }
            __syncthreads();
        }
    }
}

// NN: C[m,n] = sum_k A[m,k]*B[k,n]; A row-major (K inner), B row-major (N inner).
// B already offset to the n-block base.
__device__ __forceinline__ void mm_nn(const float* __restrict__ A, int lda,
                                      const float* __restrict__ B, int ldb,
                                      int K, float (&acc)[8][8],
                                      float (*As)[16][128], float (*Bs)[16][128]) {
    const int tid = threadIdx.x;
    const int lr = tid >> 2;              // A loader rows 0..63
    const int lc = (tid & 3) << 2;
    const int brw = tid >> 4;             // B loader row 0..15
    const int bcl = (tid & 15) << 2;      // B loader col 0..60
    const int ty = tid >> 4, tx = tid & 15;

    float4 pa[2], pb[2];
#pragma unroll
    for (int r = 0; r < 2; ++r) {
        const int row = lr + 64 * r;
        pa[r] = *(const float4*)(A + (size_t)row * lda + lc);
        pb[r] = *(const float4*)(B + (size_t)brw * ldb + bcl + 64 * r);
    }
    int buf = 0;
#pragma unroll
    for (int r = 0; r < 2; ++r) {
        const int row = lr + 64 * r;
        As[buf][lc + 0][row] = pa[r].x; As[buf][lc + 1][row] = pa[r].y;
        As[buf][lc + 2][row] = pa[r].z; As[buf][lc + 3][row] = pa[r].w;
        *(float4*)&Bs[buf][brw][bcl + 64 * r] = pb[r];
    }
    __syncthreads();

    for (int k0 = 16; k0 <= K; k0 += 16) {
        const bool more = (k0 < K);
        if (more) {
#pragma unroll
            for (int r = 0; r < 2; ++r) {
                const int row = lr + 64 * r;
                pa[r] = *(const float4*)(A + (size_t)row * lda + k0 + lc);
                pb[r] = *(const float4*)(B + (size_t)(k0 + brw) * ldb + bcl + 64 * r);
            }
        }
#pragma unroll
        for (int kk = 0; kk < 16; ++kk) {
            float ar[8], br[8];
            *(float4*)&ar[0] = *(const float4*)&As[buf][kk][ty * 8];
            *(float4*)&ar[4] = *(const float4*)&As[buf][kk][ty * 8 + 4];
            *(float4*)&br[0] = *(const float4*)&Bs[buf][kk][tx * 8];
            *(float4*)&br[4] = *(const float4*)&Bs[buf][kk][tx * 8 + 4];
#pragma unroll
            for (int i = 0; i < 8; ++i)
#pragma unroll
                for (int j = 0; j < 8; ++j)
                    acc[i][j] = fmaf(ar[i], br[j], acc[i][j]);
        }
        if (more) {
            buf ^= 1;
#pragma unroll
            for (int r = 0; r < 2; ++r) {
                const int row = lr + 64 * r;
                As[buf][lc + 0][row] = pa[r].x; As[buf][lc + 1][row] = pa[r].y;
                As[buf][lc + 2][row] = pa[r].z; As[buf][lc + 3][row] = pa[r].w;
                *(float4*)&Bs[buf][brw][bcl + 64 * r] = pb[r];
            }
            __syncthreads();
        }
    }
}

// ============================================================
// QKV projections: C = E @ W^T   (M = B*S = 8192, N = K = 1024)
// grid: (DIM/128, M/128, 3)  z selects W_q / W_k / W_v
// ============================================================
__global__ __launch_bounds__(256, 2) void qkv_kernel(const float* __restrict__ E,
                                                     const float* __restrict__ Wq,
                                                     const float* __restrict__ Wk,
                                                     const float* __restrict__ Wv) {
    __shared__ float As[2][16][128], Bs[2][16][128];
    const float* W = (blockIdx.z == 0) ? Wq : (blockIdx.z == 1) ? Wk : Wv;
    float* C = (blockIdx.z == 0) ? g_Q : (blockIdx.z == 1) ? g_K : g_V;

    const float* A = E + (size_t)blockIdx.y * 128 * DIM;
    const float* B = W + (size_t)blockIdx.x * 128 * DIM;

    float acc[8][8] = {};
    mm_nt(A, DIM, B, DIM, DIM, acc, As, Bs);

    const int ty = threadIdx.x >> 4, tx = threadIdx.x & 15;
    const int m0 = blockIdx.y * 128 + ty * 8;
    const int n0 = blockIdx.x * 128 + tx * 8;
#pragma unroll
    for (int i = 0; i < 8; ++i) {
        float4* p = (float4*)(C + (size_t)(m0 + i) * DIM + n0);
        p[0] = make_float4(acc[i][0], acc[i][1], acc[i][2], acc[i][3]);
        p[1] = make_float4(acc[i][4], acc[i][5], acc[i][6], acc[i][7]);
    }
}

// ============================================================
// scores = Q @ K^T * inv_scale + intent_bias*(mags_i*mags_j>mean) ; mask
// grid: (SEQ/128, SEQ/128, BATCH)
// Wout==nullptr -> write to g_Wscratch (device-side select; no host symbol API)
// ============================================================
__global__ __launch_bounds__(256, 2) void scores_kernel(const int* __restrict__ mask,
                                                        const float* __restrict__ bias_p,
                                                        float* Wout) {
    __shared__ float As[2][16][128], Bs[2][16][128];
    float* Wbase = Wout ? Wout : g_Wscratch;
    const int b = blockIdx.z;
    const float* A = g_Q + (size_t)b * SEQ * DIM + (size_t)blockIdx.y * 128 * DIM;
    const float* B = g_K + (size_t)b * SEQ * DIM + (size_t)blockIdx.x * 128 * DIM;

    float acc[8][8] = {};
    mm_nt(A, DIM, B, DIM, DIM, acc, As, Bs);

    const float bias = *bias_p;
    const float mean = g_mean;
    const int ty = threadIdx.x >> 4, tx = threadIdx.x & 15;
    const int q0 = blockIdx.y * 128 + ty * 8;
    const int k0 = blockIdx.x * 128 + tx * 8;

    float mq[8], mk[8];
#pragma unroll
    for (int i = 0; i < 8; ++i) mq[i] = g_mags[b * SEQ + q0 + i];
#pragma unroll
    for (int j = 0; j < 8; ++j) mk[j] = g_mags[b * SEQ + k0 + j];

    float* C = Wbase + (size_t)b * SEQ * SEQ;
    const int* Mb = mask + (size_t)b * SEQ * SEQ;
    const float inv_scale = 0.03125f;  // 1/sqrt(1024)

#pragma unroll
    for (int i = 0; i < 8; ++i) {
        int4 msk0 = *(const int4*)(Mb + (size_t)(q0 + i) * SEQ + k0);
        int4 msk1 = *(const int4*)(Mb + (size_t)(q0 + i) * SEQ + k0 + 4);
        int m[8] = {msk0.x, msk0.y, msk0.z, msk0.w, msk1.x, msk1.y, msk1.z, msk1.w};
        float v[8];
#pragma unroll
        for (int j = 0; j < 8; ++j) {
            float s = acc[i][j] * inv_scale;
            if (mq[i] * mk[j] > mean) s += bias;
            if (m[j] == 0) s = -1e9f;
            v[j] = s;
        }
        float4* p = (float4*)(C + (size_t)(q0 + i) * SEQ + k0);
        p[0] = make_float4(v[0], v[1], v[2], v[3]);
        p[1] = make_float4(v[4], v[5], v[6], v[7]);
    }
}

// ============================================================
// row softmax over SEQ, in place; one block per row
// ============================================================
__global__ __launch_bounds__(256) void softmax_kernel(float* Wout) {
    float* Wbase = Wout ? Wout : g_Wscratch;
    const int row = blockIdx.x;
    float* p = Wbase + (size_t)row * SEQ;
    const int tid = threadIdx.x;

    float v[8];
    *(float4*)&v[0] = *(const float4*)&p[tid * 8];
    *(float4*)&v[4] = *(const float4*)&p[tid * 8 + 4];

    float m = v[0];
#pragma unroll
    for (int i = 1; i < 8; ++i) m = fmaxf(m, v[i]);
#pragma unroll
    for (int off = 16; off > 0; off >>= 1)
        m = fmaxf(m, __shfl_xor_sync(0xFFFFFFFFu, m, off));

    __shared__ float redm[8], reds[8];
    if ((tid & 31) == 0) redm[tid >> 5] = m;
    __syncthreads();
    float gm = redm[0];
#pragma unroll
    for (int w = 1; w < 8; ++w) gm = fmaxf(gm, redm[w]);

    float sum = 0.f;
#pragma unroll
    for (int i = 0; i < 8; ++i) {
        v[i] = __expf(v[i] - gm);
        sum += v[i];
    }
#pragma unroll
    for (int off = 16; off > 0; off >>= 1)
        sum += __shfl_xor_sync(0xFFFFFFFFu, sum, off);
    if ((tid & 31) == 0) reds[tid >> 5] = sum;
    __syncthreads();
    float gs = reds[0];
#pragma unroll
    for (int w = 1; w < 8; ++w) gs += reds[w];
    const float inv = 1.0f / gs;

#pragma unroll
    for (int i = 0; i < 8; ++i) v[i] *= inv;
    *(float4*)&p[tid * 8]     = *(const float4*)&v[0];
    *(float4*)&p[tid * 8 + 4] = *(const float4*)&v[4];
}

// ============================================================
// attended = A @ V   (NN GEMM, M=SEQ, N=DIM, K=SEQ per batch)
// grid: (DIM/128, SEQ/128, BATCH)
// ============================================================
__global__ __launch_bounds__(256, 2) void av_kernel(float* Win,
                                                    float* __restrict__ Out) {
    __shared__ float As[2][16][128], Bs[2][16][128];
    const float* Wbase = Win ? Win : g_Wscratch;
    const int b = blockIdx.z;
    const float* A = Wbase + (size_t)b * SEQ * SEQ + (size_t)blockIdx.y * 128 * SEQ;
    const float* B = g_V + (size_t)b * SEQ * DIM + blockIdx.x * 128;

    float acc[8][8] = {};
    mm_nn(A, SEQ, B, DIM, SEQ, acc, As, Bs);

    const int ty = threadIdx.x >> 4, tx = threadIdx.x & 15;
    const int m0 = blockIdx.y * 128 + ty * 8;
    const int n0 = blockIdx.x * 128 + tx * 8;
    float* C = Out + (size_t)b * SEQ * DIM;
#pragma unroll
    for (int i = 0; i < 8; ++i) {
        float4* p = (float4*)(C + (size_t)(m0 + i) * DIM + n0);
        p[0] = make_float4(acc[i][0], acc[i][1], acc[i][2], acc[i][3]);
        p[1] = make_float4(acc[i][4], acc[i][5], acc[i][6], acc[i][7]);
    }
}

// ============================================================
extern "C" void kernel_launch(void* const* d_in, const int* in_sizes, int n_in,
                              void* d_out, int out_size) {
    const float* E    = (const float*)d_in[0];
    const float* Wq   = (const float*)d_in[1];
    const float* Wk   = (const float*)d_in[2];
    const float* Wv   = (const float*)d_in[3];
    const float* bias = (const float*)d_in[4];
    const int*   mask = (const int*)d_in[5];

    float* out = (float*)d_out;
    float* attended = out;  // [B,S,D]
    // weights [B,S,S]: in d_out if it has room for the tuple, else device scratch
    // (selected device-side via nullptr -> g_Wscratch; no host symbol lookup)
    const long long need = (long long)BATCH * SEQ * DIM + (long long)BATCH * SEQ * SEQ;
    float* weights = ((long long)out_size >= need)
                       ? out + (size_t)BATCH * SEQ * DIM
                       : nullptr;

    mags_kernel<<<BATCH * SEQ, 256>>>(E);
    mean_kernel<<<1, 256>>>();
    qkv_kernel<<<dim3(DIM / 128, (BATCH * SEQ) / 128, 3), 256>>>(E, Wq, Wk, Wv);
    scores_kernel<<<dim3(SEQ / 128, SEQ / 128, BATCH), 256>>>(mask, bias, weights);
    softmax_kernel<<<BATCH * SEQ, 256>>>(weights);
    av_kernel<<<dim3(DIM / 128, SEQ / 128, BATCH), 256>>>(weights, attended);
}

// round 17
// speedup vs baseline: 1.0975x; 1.0975x over previous
#include <cuda_runtime.h>
#include <math.h>
#include <stdint.h>

#define BATCH 4
#define SEQ   2048
#define DIM   1024

// ---- static device scratch (no allocations allowed) ----
__device__ float g_Q[BATCH * SEQ * DIM];
__device__ float g_K[BATCH * SEQ * DIM];
__device__ float g_V[BATCH * SEQ * DIM];
__device__ float g_mags[BATCH * SEQ];
__device__ float g_mean;
__device__ float g_Wscratch[BATCH * SEQ * SEQ];  // fallback if weights not in d_out

// packed f32x2 helpers (FFMA2 path — sm_103a, PTX-only)
__device__ __forceinline__ unsigned long long splat_f32x2(float a) {
    unsigned long long r;
    uint32_t au = __float_as_uint(a);
    asm("mov.b64 %0, {%1, %1};" : "=l"(r) : "r"(au));
    return r;
}
__device__ __forceinline__ void fma_f32x2(unsigned long long& d,
                                          unsigned long long a,
                                          unsigned long long b) {
    asm("fma.rn.f32x2 %0, %1, %2, %0;" : "+l"(d) : "l"(a), "l"(b));
}
// extract element j (0=lo,1=hi) — compile-time j under full unroll
__device__ __forceinline__ float f32x2_get(unsigned long long v, int j) {
    return __uint_as_float(j ? (uint32_t)(v >> 32) : (uint32_t)v);
}

// ============================================================
// per-token L2 norms (float4 loads + warp-shuffle reduction)
// ============================================================
__global__ __launch_bounds__(256) void mags_kernel(const float* __restrict__ E) {
    const int token = blockIdx.x;                  // 0 .. B*S-1
    const float* x = E + (size_t)token * DIM;
    const int tid = threadIdx.x;
    float4 v = *(const float4*)(x + tid * 4);
    float s = v.x * v.x + v.y * v.y + v.z * v.z + v.w * v.w;
#pragma unroll
    for (int off = 16; off > 0; off >>= 1)
        s += __shfl_xor_sync(0xFFFFFFFFu, s, off);
    __shared__ float red[8];
    if ((tid & 31) == 0) red[tid >> 5] = s;
    __syncthreads();
    if (tid < 8) {
        float t = red[tid];
#pragma unroll
        for (int off = 4; off > 0; off >>= 1)
            t += __shfl_xor_sync(0xFFu, t, off);
        if (tid == 0) g_mags[token] = sqrtf(t);
    }
}

// ============================================================
// global mean of outer product:  mean = (1/(B*S*S)) * sum_b (sum_s mags)^2
// ============================================================
__global__ __launch_bounds__(256) void mean_kernel() {
    __shared__ double red[256];
    const int tid = threadIdx.x;
    double total = 0.0;
    for (int b = 0; b < BATCH; ++b) {
        double s = 0.0;
        for (int i = tid; i < SEQ; i += 256) s += (double)g_mags[b * SEQ + i];
        red[tid] = s;
        __syncthreads();
        for (int off = 128; off > 0; off >>= 1) {
            if (tid < off) red[tid] += red[tid + off];
            __syncthreads();
        }
        if (tid == 0) total += red[0] * red[0];
        __syncthreads();
    }
    if (tid == 0)
        g_mean = (float)(total / ((double)BATCH * (double)SEQ * (double)SEQ));
}

// ============================================================
// Double-buffered SGEMM mainloops with packed f32x2 FMA:
// 128x128 tile, BK=16, 256 threads, 8x8 per thread (acc as 8x4 f32x2).
// ============================================================

// shared compute block: As/Bs fragment load + 8x4 packed FMA
__device__ __forceinline__ void compute_block(const float (*As)[128],
                                              const float (*Bs)[128],
                                              int ty, int tx,
                                              unsigned long long (&acc2)[8][4]) {
#pragma unroll
    for (int kk = 0; kk < 16; ++kk) {
        float ar[8];
        *(float4*)&ar[0] = *(const float4*)&As[kk][ty * 8];
        *(float4*)&ar[4] = *(const float4*)&As[kk][ty * 8 + 4];
        unsigned long long b2[4];
        {
            ulonglong2 t0 = *(const ulonglong2*)&Bs[kk][tx * 8];
            ulonglong2 t1 = *(const ulonglong2*)&Bs[kk][tx * 8 + 4];
            b2[0] = t0.x; b2[1] = t0.y; b2[2] = t1.x; b2[3] = t1.y;
        }
#pragma unroll
        for (int i = 0; i < 8; ++i) {
            unsigned long long a2 = splat_f32x2(ar[i]);
#pragma unroll
            for (int j = 0; j < 4; ++j)
                fma_f32x2(acc2[i][j], a2, b2[j]);
        }
    }
}

// NT: C[m,n] = sum_k A[m,k]*B[n,k]; both row-major, K contiguous.
__device__ __forceinline__ void mm_nt(const float* __restrict__ A, int lda,
                                      const float* __restrict__ B, int ldb,
                                      int K, unsigned long long (&acc2)[8][4],
                                      float (*As)[16][128], float (*Bs)[16][128]) {
    const int tid = threadIdx.x;
    const int lr = tid >> 2;              // 0..63
    const int lc = (tid & 3) << 2;        // 0,4,8,12
    const int ty = tid >> 4, tx = tid & 15;

    float4 pa[2], pb[2];
#pragma unroll
    for (int r = 0; r < 2; ++r) {
        const int row = lr + 64 * r;
        pa[r] = *(const float4*)(A + (size_t)row * lda + lc);
        pb[r] = *(const float4*)(B + (size_t)row * ldb + lc);
    }
    int buf = 0;
#pragma unroll
    for (int r = 0; r < 2; ++r) {
        const int row = lr + 64 * r;
        As[buf][lc + 0][row] = pa[r].x; As[buf][lc + 1][row] = pa[r].y;
        As[buf][lc + 2][row] = pa[r].z; As[buf][lc + 3][row] = pa[r].w;
        Bs[buf][lc + 0][row] = pb[r].x; Bs[buf][lc + 1][row] = pb[r].y;
        Bs[buf][lc + 2][row] = pb[r].z; Bs[buf][lc + 3][row] = pb[r].w;
    }
    __syncthreads();

    for (int k0 = 16; k0 <= K; k0 += 16) {
        const bool more = (k0 < K);
        if (more) {
#pragma unroll
            for (int r = 0; r < 2; ++r) {
                const int row = lr + 64 * r;
                pa[r] = *(const float4*)(A + (size_t)row * lda + k0 + lc);
                pb[r] = *(const float4*)(B + (size_t)row * ldb + k0 + lc);
            }
        }
        compute_block(As[buf], Bs[buf], ty, tx, acc2);
        if (more) {
            buf ^= 1;
#pragma unroll
            for (int r = 0; r < 2; ++r) {
                const int row = lr + 64 * r;
                As[buf][lc + 0][row] = pa[r].x; As[buf][lc + 1][row] = pa[r].y;
                As[buf][lc + 2][row] = pa[r].z; As[buf][lc + 3][row] = pa[r].w;
                Bs[buf][lc + 0][row] = pb[r].x; Bs[buf][lc + 1][row] = pb[r].y;
                Bs[buf][lc + 2][row] = pb[r].z; Bs[buf][lc + 3][row] = pb[r].w;
            }
            __syncthreads();
        }
    }
}

// NN: C[m,n] = sum_k A[m,k]*B[k,n]; A row-major (K inner), B row-major (N inner).
__device__ __forceinline__ void mm_nn(const float* __restrict__ A, int lda,
                                      const float* __restrict__ B, int ldb,
                                      int K, unsigned long long (&acc2)[8][4],
                                      float (*As)[16][128], float (*Bs)[16][128]) {
    const int tid = threadIdx.x;
    const int lr = tid >> 2;              // A loader rows 0..63
    const int lc = (tid & 3) << 2;
    const int brw = tid >> 4;             // B loader row 0..15
    const int bcl = (tid & 15) << 2;      // B loader col 0..60
    const int ty = tid >> 4, tx = tid & 15;

    float4 pa[2], pb[2];
#pragma unroll
    for (int r = 0; r < 2; ++r) {
        const int row = lr + 64 * r;
        pa[r] = *(const float4*)(A + (size_t)row * lda + lc);
        pb[r] = *(const float4*)(B + (size_t)brw * ldb + bcl + 64 * r);
    }
    int buf = 0;
#pragma unroll
    for (int r = 0; r < 2; ++r) {
        const int row = lr + 64 * r;
        As[buf][lc + 0][row] = pa[r].x; As[buf][lc + 1][row] = pa[r].y;
        As[buf][lc + 2][row] = pa[r].z; As[buf][lc + 3][row] = pa[r].w;
        *(float4*)&Bs[buf][brw][bcl + 64 * r] = pb[r];
    }
    __syncthreads();

    for (int k0 = 16; k0 <= K; k0 += 16) {
        const bool more = (k0 < K);
        if (more) {
#pragma unroll
            for (int r = 0; r < 2; ++r) {
                const int row = lr + 64 * r;
                pa[r] = *(const float4*)(A + (size_t)row * lda + k0 + lc);
                pb[r] = *(const float4*)(B + (size_t)(k0 + brw) * ldb + bcl + 64 * r);
            }
        }
        compute_block(As[buf], Bs[buf], ty, tx, acc2);
        if (more) {
            buf ^= 1;
#pragma unroll
            for (int r = 0; r < 2; ++r) {
                const int row = lr + 64 * r;
                As[buf][lc + 0][row] = pa[r].x; As[buf][lc + 1][row] = pa[r].y;
                As[buf][lc + 2][row] = pa[r].z; As[buf][lc + 3][row] = pa[r].w;
                *(float4*)&Bs[buf][brw][bcl + 64 * r] = pb[r];
            }
            __syncthreads();
        }
    }
}

// ============================================================
// QKV projections: C = E @ W^T   (M = B*S = 8192, N = K = 1024)
// ============================================================
__global__ __launch_bounds__(256, 2) void qkv_kernel(const float* __restrict__ E,
                                                     const float* __restrict__ Wq,
                                                     const float* __restrict__ Wk,
                                                     const float* __restrict__ Wv) {
    __shared__ float As[2][16][128], Bs[2][16][128];
    const float* W = (blockIdx.z == 0) ? Wq : (blockIdx.z == 1) ? Wk : Wv;
    float* C = (blockIdx.z == 0) ? g_Q : (blockIdx.z == 1) ? g_K : g_V;

    const float* A = E + (size_t)blockIdx.y * 128 * DIM;
    const float* B = W + (size_t)blockIdx.x * 128 * DIM;

    unsigned long long acc2[8][4] = {};
    mm_nt(A, DIM, B, DIM, DIM, acc2, As, Bs);

    const int ty = threadIdx.x >> 4, tx = threadIdx.x & 15;
    const int m0 = blockIdx.y * 128 + ty * 8;
    const int n0 = blockIdx.x * 128 + tx * 8;
#pragma unroll
    for (int i = 0; i < 8; ++i) {
        float4* p = (float4*)(C + (size_t)(m0 + i) * DIM + n0);
        p[0] = make_float4(f32x2_get(acc2[i][0], 0), f32x2_get(acc2[i][0], 1),
                           f32x2_get(acc2[i][1], 0), f32x2_get(acc2[i][1], 1));
        p[1] = make_float4(f32x2_get(acc2[i][2], 0), f32x2_get(acc2[i][2], 1),
                           f32x2_get(acc2[i][3], 0), f32x2_get(acc2[i][3], 1));
    }
}

// ============================================================
// scores = Q @ K^T * inv_scale + intent_bias*(mags_i*mags_j>mean) ; mask
// Wout==nullptr -> write to g_Wscratch
// ============================================================
__global__ __launch_bounds__(256, 2) void scores_kernel(const int* __restrict__ mask,
                                                        const float* __restrict__ bias_p,
                                                        float* Wout) {
    __shared__ float As[2][16][128], Bs[2][16][128];
    float* Wbase = Wout ? Wout : g_Wscratch;
    const int b = blockIdx.z;
    const float* A = g_Q + (size_t)b * SEQ * DIM + (size_t)blockIdx.y * 128 * DIM;
    const float* B = g_K + (size_t)b * SEQ * DIM + (size_t)blockIdx.x * 128 * DIM;

    unsigned long long acc2[8][4] = {};
    mm_nt(A, DIM, B, DIM, DIM, acc2, As, Bs);

    const float bias = *bias_p;
    const float mean = g_mean;
    const int ty = threadIdx.x >> 4, tx = threadIdx.x & 15;
    const int q0 = blockIdx.y * 128 + ty * 8;
    const int k0 = blockIdx.x * 128 + tx * 8;

    float mq[8], mk[8];
#pragma unroll
    for (int i = 0; i < 8; ++i) mq[i] = g_mags[b * SEQ + q0 + i];
#pragma unroll
    for (int j = 0; j < 8; ++j) mk[j] = g_mags[b * SEQ + k0 + j];

    float* C = Wbase + (size_t)b * SEQ * SEQ;
    const int* Mb = mask + (size_t)b * SEQ * SEQ;
    const float inv_scale = 0.03125f;  // 1/sqrt(1024)

#pragma unroll
    for (int i = 0; i < 8; ++i) {
        int4 msk0 = *(const int4*)(Mb + (size_t)(q0 + i) * SEQ + k0);
        int4 msk1 = *(const int4*)(Mb + (size_t)(q0 + i) * SEQ + k0 + 4);
        int m[8] = {msk0.x, msk0.y, msk0.z, msk0.w, msk1.x, msk1.y, msk1.z, msk1.w};
        float v[8];
#pragma unroll
        for (int j = 0; j < 8; ++j) {
            float s = f32x2_get(acc2[i][j >> 1], j & 1) * inv_scale;
            if (mq[i] * mk[j] > mean) s += bias;
            if (m[j] == 0) s = -1e9f;
            v[j] = s;
        }
        float4* p = (float4*)(C + (size_t)(q0 + i) * SEQ + k0);
        p[0] = make_float4(v[0], v[1], v[2], v[3]);
        p[1] = make_float4(v[4], v[5], v[6], v[7]);
    }
}

// ============================================================
// row softmax over SEQ, in place; one block per row
// ============================================================
__global__ __launch_bounds__(256) void softmax_kernel(float* Wout) {
    float* Wbase = Wout ? Wout : g_Wscratch;
    const int row = blockIdx.x;
    float* p = Wbase + (size_t)row * SEQ;
    const int tid = threadIdx.x;

    float v[8];
    *(float4*)&v[0] = *(const float4*)&p[tid * 8];
    *(float4*)&v[4] = *(const float4*)&p[tid * 8 + 4];

    float m = v[0];
#pragma unroll
    for (int i = 1; i < 8; ++i) m = fmaxf(m, v[i]);
#pragma unroll
    for (int off = 16; off > 0; off >>= 1)
        m = fmaxf(m, __shfl_xor_sync(0xFFFFFFFFu, m, off));

    __shared__ float redm[8], reds[8];
    if ((tid & 31) == 0) redm[tid >> 5] = m;
    __syncthreads();
    float gm = redm[0];
#pragma unroll
    for (int w = 1; w < 8; ++w) gm = fmaxf(gm, redm[w]);

    float sum = 0.f;
#pragma unroll
    for (int i = 0; i < 8; ++i) {
        v[i] = __expf(v[i] - gm);
        sum += v[i];
    }
#pragma unroll
    for (int off = 16; off > 0; off >>= 1)
        sum += __shfl_xor_sync(0xFFFFFFFFu, sum, off);
    if ((tid & 31) == 0) reds[tid >> 5] = sum;
    __syncthreads();
    float gs = reds[0];
#pragma unroll
    for (int w = 1; w < 8; ++w) gs += reds[w];
    const float inv = 1.0f / gs;

#pragma unroll
    for (int i = 0; i < 8; ++i) v[i] *= inv;
    *(float4*)&p[tid * 8]     = *(const float4*)&v[0];
    *(float4*)&p[tid * 8 + 4] = *(const float4*)&v[4];
}

// ============================================================
// attended = A @ V   (NN GEMM, M=SEQ, N=DIM, K=SEQ per batch)
// ============================================================
__global__ __launch_bounds__(256, 2) void av_kernel(float* Win,
                                                    float* __restrict__ Out) {
    __shared__ float As[2][16][128], Bs[2][16][128];
    const float* Wbase = Win ? Win : g_Wscratch;
    const int b = blockIdx.z;
    const float* A = Wbase + (size_t)b * SEQ * SEQ + (size_t)blockIdx.y * 128 * SEQ;
    const float* B = g_V + (size_t)b * SEQ * DIM + blockIdx.x * 128;

    unsigned long long acc2[8][4] = {};
    mm_nn(A, SEQ, B, DIM, SEQ, acc2, As, Bs);

    const int ty = threadIdx.x >> 4, tx = threadIdx.x & 15;
    const int m0 = blockIdx.y * 128 + ty * 8;
    const int n0 = blockIdx.x * 128 + tx * 8;
    float* C = Out + (size_t)b * SEQ * DIM;
#pragma unroll
    for (int i = 0; i < 8; ++i) {
        float4* p = (float4*)(C + (size_t)(m0 + i) * DIM + n0);
        p[0] = make_float4(f32x2_get(acc2[i][0], 0), f32x2_get(acc2[i][0], 1),
                           f32x2_get(acc2[i][1], 0), f32x2_get(acc2[i][1], 1));
        p[1] = make_float4(f32x2_get(acc2[i][2], 0), f32x2_get(acc2[i][2], 1),
                           f32x2_get(acc2[i][3], 0), f32x2_get(acc2[i][3], 1));
    }
}

// ============================================================
extern "C" void kernel_launch(void* const* d_in, const int* in_sizes, int n_in,
                              void* d_out, int out_size) {
    const float* E    = (const float*)d_in[0];
    const float* Wq   = (const float*)d_in[1];
    const float* Wk   = (const float*)d_in[2];
    const float* Wv   = (const float*)d_in[3];
    const float* bias = (const float*)d_in[4];
    const int*   mask = (const int*)d_in[5];

    float* out = (float*)d_out;
    float* attended = out;  // [B,S,D]
    const long long need = (long long)BATCH * SEQ * DIM + (long long)BATCH * SEQ * SEQ;
    float* weights = ((long long)out_size >= need)
                       ? out + (size_t)BATCH * SEQ * DIM
                       : nullptr;

    mags_kernel<<<BATCH * SEQ, 256>>>(E);
    mean_kernel<<<1, 256>>>();
    qkv_kernel<<<dim3(DIM / 128, (BATCH * SEQ) / 128, 3), 256>>>(E, Wq, Wk, Wv);
    scores_kernel<<<dim3(SEQ / 128, SEQ / 128, BATCH), 256>>>(mask, bias, weights);
    softmax_kernel<<<BATCH * SEQ, 256>>>(weights);
    av_kernel<<<dim3(DIM / 128, SEQ / 128, BATCH), 256>>>(weights, attended);
}